// round 1
// baseline (speedup 1.0000x reference)
#include <cuda_runtime.h>
#include <cstdint>

#define MROWS 262144
#define HDIM  128
#define NEDGE 2097152
#define NSEG  16384

// ---- scratch (device-global, no allocation) ----
__device__ float g_aggr[MROWS * HDIM];   // (1+eps)*h + sum_{j->i} h_j
__device__ float g_hc[MROWS * HDIM];     // masked MLP output
__device__ float g_hsum[NSEG * HDIM];    // segment sums -> x_agg (in place)
__device__ float g_cnt[NSEG];            // valid counts per segment
__device__ int   g_ei64, g_nid64, g_vb8; // dtype detection flags

typedef unsigned long long ull;

__device__ __forceinline__ ull pk2(float x) {
    unsigned u = __float_as_uint(x); ull d;
    asm("mov.b64 %0, {%1, %2};" : "=l"(d) : "r"(u), "r"(u));
    return d;
}
__device__ __forceinline__ ull pk(float x, float y) {
    ull d;
    asm("mov.b64 %0, {%1, %2};" : "=l"(d) : "r"(__float_as_uint(x)), "r"(__float_as_uint(y)));
    return d;
}
__device__ __forceinline__ float2 upk(ull v) {
    unsigned a, b;
    asm("mov.b64 {%0, %1}, %2;" : "=r"(a), "=r"(b) : "l"(v));
    return make_float2(__uint_as_float(a), __uint_as_float(b));
}
__device__ __forceinline__ void fma2(ull& d, ull a, ull b) {
    asm("fma.rn.f32x2 %0, %1, %2, %0;" : "+l"(d) : "l"(a), "l"(b));
}

__device__ __forceinline__ long long ld_idx(const void* p, int i, int is64) {
    return is64 ? ((const long long*)p)[i] : (long long)((const int*)p)[i];
}
__device__ __forceinline__ float ld_valid(const void* p, int i, int b8) {
    return b8 ? (((const unsigned char*)p)[i] ? 1.0f : 0.0f)
              : (((const int*)p)[i] ? 1.0f : 0.0f);
}

// ---- dtype detection: int64-vs-int32 indices, byte-vs-int bools ----
__global__ void k_detect(const unsigned* ei, const unsigned* nid, const unsigned* vld) {
    __shared__ int cnt[3];
    int t = threadIdx.x;
    if (t < 3) cnt[t] = 0;
    __syncthreads();
    int nz = 0;
    for (int i = t; i < 1024; i += 256) nz += (ei[2 * i + 1] != 0u);
    if (nz) atomicAdd(&cnt[0], nz);
    nz = 0;
    for (int i = t; i < 1024; i += 256) nz += (nid[2 * i + 1] != 0u);
    if (nz) atomicAdd(&cnt[1], nz);
    nz = 0;
    for (int i = t; i < 256; i += 256) nz += (vld[i] > 1u);
    if (nz) atomicAdd(&cnt[2], nz);
    __syncthreads();
    if (t == 0) {
        g_ei64  = (cnt[0] < 512); // int64: odd 32-bit words are all zero
        g_nid64 = (cnt[1] < 512);
        g_vb8   = (cnt[2] > 0);   // byte-packed bools look like big ints
    }
}

// ---- init: aggr = (1+eps)*h ; zero hsum, cnt ----
__global__ void k_init(const float4* __restrict__ h4, const float* __restrict__ epsp) {
    int i = blockIdx.x * blockDim.x + threadIdx.x;
    const int A4 = MROWS * HDIM / 4, NH4 = NSEG * HDIM / 4, C4 = NSEG / 4;
    if (i < A4) {
        float e1 = 1.0f + *epsp;
        float4 v = h4[i];
        v.x *= e1; v.y *= e1; v.z *= e1; v.w *= e1;
        ((float4*)g_aggr)[i] = v;
    } else if (i < A4 + NH4) {
        ((float4*)g_hsum)[i - A4] = make_float4(0.f, 0.f, 0.f, 0.f);
    } else if (i < A4 + NH4 + C4) {
        ((float4*)g_cnt)[i - A4 - NH4] = make_float4(0.f, 0.f, 0.f, 0.f);
    }
}

// ---- edge scatter: aggr[dst] += h[src], one warp per edge, RED.128 ----
__global__ __launch_bounds__(256) void k_edges(const float* __restrict__ h,
                                               const void* __restrict__ ei) {
    int e = blockIdx.x * 8 + (threadIdx.x >> 5);
    int lane = threadIdx.x & 31;
    long long s, d;
    if (g_ei64) {
        const long long* p = (const long long*)ei;
        s = p[e]; d = p[NEDGE + e];
    } else {
        const int* p = (const int*)ei;
        s = p[e]; d = p[NEDGE + e];
    }
    float4 v = *(const float4*)(h + s * HDIM + lane * 4);
    atomicAdd((float4*)(g_aggr + d * HDIM + lane * 4), v);
}

// ---- valid counts per segment ----
__global__ void k_count(const void* __restrict__ nid, const void* __restrict__ vld) {
    int i = blockIdx.x * blockDim.x + threadIdx.x;
    if (i >= MROWS) return;
    if (ld_valid(vld, i, g_vb8) > 0.f) {
        long long n = ld_idx(nid, i, g_nid64);
        if (n < 0) n = 0;
        atomicAdd(&g_cnt[(int)n], 1.0f);
    }
}

// ---- FFMA2 inner GEMM: acc[8 row-pairs][4 cols] += AsT(k-major) * Bs ----
__device__ __forceinline__ void gemm_acc(const float* __restrict__ AsT,
                                         const float* __restrict__ Bs,
                                         ull acc[8][4], int r0, int c0) {
#pragma unroll 4
    for (int k = 0; k < 128; ++k) {
        ull a[8];
        const ulonglong2* ap = (const ulonglong2*)(AsT + k * 132 + r0);
#pragma unroll
        for (int q = 0; q < 4; ++q) {
            ulonglong2 t = ap[q];
            a[2 * q] = t.x; a[2 * q + 1] = t.y;
        }
        float4 bv = *(const float4*)(Bs + k * 128 + c0);
        ull b0 = pk2(bv.x), b1 = pk2(bv.y), b2 = pk2(bv.z), b3 = pk2(bv.w);
#pragma unroll
        for (int p = 0; p < 8; ++p) {
            fma2(acc[p][0], a[p], b0);
            fma2(acc[p][1], a[p], b1);
            fma2(acc[p][2], a[p], b2);
            fma2(acc[p][3], a[p], b3);
        }
    }
}

// ---- fused MLP: relu(Z@w1+b1)@w2+b2, mask, write hc, scatter-add hsum ----
__global__ __launch_bounds__(256) void k_mlp(const float* __restrict__ w1,
                                             const float* __restrict__ b1,
                                             const float* __restrict__ w2,
                                             const float* __restrict__ b2,
                                             const void* __restrict__ nid,
                                             const void* __restrict__ vld) {
    extern __shared__ float s[];
    float* AsT = s;                         // [128][132] k-major operand
    float* Bs  = s + 128 * 132;             // [128][128]
    int*   snid = (int*)(Bs + 128 * 128);   // [128]
    float* svf  = (float*)(snid + 128);     // [128]

    const int tid = threadIdx.x;
    const int rbase = blockIdx.x * 128;

    if (tid < 128) {
        long long n = ld_idx(nid, rbase + tid, g_nid64);
        if (n < 0) n = 0;
        snid[tid] = (int)n;
        svf[tid]  = ld_valid(vld, rbase + tid, g_vb8);
    }

    const int c  = tid & 127;
    const int rq = (tid >> 7) * 4;
    for (int rr = 0; rr < 128; rr += 8) {
        int r = rr + rq;
        float4 v;
        v.x = g_aggr[(rbase + r + 0) * HDIM + c];
        v.y = g_aggr[(rbase + r + 1) * HDIM + c];
        v.z = g_aggr[(rbase + r + 2) * HDIM + c];
        v.w = g_aggr[(rbase + r + 3) * HDIM + c];
        *(float4*)(AsT + c * 132 + r) = v;
    }
    for (int i = tid; i < 128 * 32; i += 256)
        ((float4*)Bs)[i] = ((const float4*)w1)[i];
    __syncthreads();

    const int warp = tid >> 5, lane = tid & 31;
    const int r0 = (warp >> 2) * 64 + (lane >> 3) * 16;
    const int c0 = (warp & 3) * 32 + (lane & 7) * 4;

    ull acc[8][4];
#pragma unroll
    for (int p = 0; p < 8; ++p)
#pragma unroll
        for (int j = 0; j < 4; ++j) acc[p][j] = 0ull;

    gemm_acc(AsT, Bs, acc, r0, c0);

    float bb[4];
#pragma unroll
    for (int j = 0; j < 4; ++j) bb[j] = __ldg(b1 + c0 + j);
#pragma unroll
    for (int p = 0; p < 8; ++p)
#pragma unroll
        for (int j = 0; j < 4; ++j) {
            float2 v = upk(acc[p][j]);
            v.x = fmaxf(v.x + bb[j], 0.f);
            v.y = fmaxf(v.y + bb[j], 0.f);
            acc[p][j] = pk(v.x, v.y);
        }
    __syncthreads();
    // T^T into AsT (new k dimension = old cols)
#pragma unroll
    for (int j = 0; j < 4; ++j) {
        float4* dst = (float4*)(AsT + (c0 + j) * 132 + r0);
#pragma unroll
        for (int q = 0; q < 4; ++q) {
            float2 a0 = upk(acc[2 * q][j]), a1 = upk(acc[2 * q + 1][j]);
            dst[q] = make_float4(a0.x, a0.y, a1.x, a1.y);
        }
    }
    for (int i = tid; i < 128 * 32; i += 256)
        ((float4*)Bs)[i] = ((const float4*)w2)[i];
    __syncthreads();

#pragma unroll
    for (int p = 0; p < 8; ++p)
#pragma unroll
        for (int j = 0; j < 4; ++j) acc[p][j] = 0ull;
    gemm_acc(AsT, Bs, acc, r0, c0);

#pragma unroll
    for (int j = 0; j < 4; ++j) bb[j] = __ldg(b2 + c0 + j);

#pragma unroll
    for (int p = 0; p < 8; ++p) {
        int rA = r0 + 2 * p, rB = rA + 1;
        float2 cj[4];
#pragma unroll
        for (int j = 0; j < 4; ++j) cj[j] = upk(acc[p][j]);
        float vfA = svf[rA], vfB = svf[rB];
        float4 hA = make_float4((cj[0].x + bb[0]) * vfA, (cj[1].x + bb[1]) * vfA,
                                (cj[2].x + bb[2]) * vfA, (cj[3].x + bb[3]) * vfA);
        float4 hB = make_float4((cj[0].y + bb[0]) * vfB, (cj[1].y + bb[1]) * vfB,
                                (cj[2].y + bb[2]) * vfB, (cj[3].y + bb[3]) * vfB);
        *(float4*)(g_hc + (rbase + rA) * HDIM + c0) = hA;
        *(float4*)(g_hc + (rbase + rB) * HDIM + c0) = hB;
        if (vfA > 0.f) atomicAdd((float4*)(g_hsum + snid[rA] * HDIM + c0), hA);
        if (vfB > 0.f) atomicAdd((float4*)(g_hsum + snid[rB] * HDIM + c0), hB);
    }
}

// ---- x_agg = hsum / max(cnt,1), in place ----
__global__ void k_div() {
    int i4 = blockIdx.x * blockDim.x + threadIdx.x;
    if (i4 >= NSEG * HDIM / 4) return;
    int row = i4 >> 5;
    float inv = 1.0f / fmaxf(g_cnt[row], 1.0f);
    float4 v = ((float4*)g_hsum)[i4];
    v.x *= inv; v.y *= inv; v.z *= inv; v.w *= inv;
    ((float4*)g_hsum)[i4] = v;
}

// ---- out = (relu([hc|x_cross]@ow+ob)*bn_s + bn_b + h) * valid ----
__global__ __launch_bounds__(256) void k_out(const float* __restrict__ h,
                                             const float* __restrict__ ow,
                                             const float* __restrict__ ob,
                                             const float* __restrict__ bnw,
                                             const float* __restrict__ bnb,
                                             const void* __restrict__ nid,
                                             const void* __restrict__ vld,
                                             float* __restrict__ out) {
    extern __shared__ float s[];
    float* AsT = s;
    float* Bs  = s + 128 * 132;
    int*   snid = (int*)(Bs + 128 * 128);
    float* svf  = (float*)(snid + 128);

    const int tid = threadIdx.x;
    const int rbase = blockIdx.x * 128;

    if (tid < 128) {
        long long n = ld_idx(nid, rbase + tid, g_nid64);
        if (n < 0) n = 0;
        snid[tid] = (int)n;
        svf[tid]  = ld_valid(vld, rbase + tid, g_vb8);
    }
    __syncthreads();

    const int warp = tid >> 5, lane = tid & 31;
    const int r0 = (warp >> 2) * 64 + (lane >> 3) * 16;
    const int c0 = (warp & 3) * 32 + (lane & 7) * 4;
    const int c  = tid & 127;
    const int rq = (tid >> 7) * 4;

    ull acc[8][4];
#pragma unroll
    for (int p = 0; p < 8; ++p)
#pragma unroll
        for (int j = 0; j < 4; ++j) acc[p][j] = 0ull;

    for (int chunk = 0; chunk < 2; ++chunk) {
        for (int rr = 0; rr < 128; rr += 8) {
            int r = rr + rq;
            float4 v;
            if (chunk == 0) {
                v.x = g_hc[(rbase + r + 0) * HDIM + c];
                v.y = g_hc[(rbase + r + 1) * HDIM + c];
                v.z = g_hc[(rbase + r + 2) * HDIM + c];
                v.w = g_hc[(rbase + r + 3) * HDIM + c];
            } else {
                v.x = g_hsum[snid[r + 0] * HDIM + c] * svf[r + 0];
                v.y = g_hsum[snid[r + 1] * HDIM + c] * svf[r + 1];
                v.z = g_hsum[snid[r + 2] * HDIM + c] * svf[r + 2];
                v.w = g_hsum[snid[r + 3] * HDIM + c] * svf[r + 3];
            }
            *(float4*)(AsT + c * 132 + r) = v;
        }
        for (int i = tid; i < 128 * 32; i += 256)
            ((float4*)Bs)[i] = ((const float4*)ow)[chunk * 4096 + i];
        __syncthreads();
        gemm_acc(AsT, Bs, acc, r0, c0);
        __syncthreads();
    }

    float obv[4], swv[4], sbv[4];
    const float rs = rsqrtf(1.0f + 1e-5f);
#pragma unroll
    for (int j = 0; j < 4; ++j) {
        obv[j] = __ldg(ob + c0 + j);
        swv[j] = __ldg(bnw + c0 + j) * rs;
        sbv[j] = __ldg(bnb + c0 + j);
    }

#pragma unroll
    for (int p = 0; p < 8; ++p) {
        int rA = r0 + 2 * p, rB = rA + 1;
        float2 cj[4];
#pragma unroll
        for (int j = 0; j < 4; ++j) cj[j] = upk(acc[p][j]);
        float vfA = svf[rA], vfB = svf[rB];
        float4 hA4 = *(const float4*)(h + (rbase + rA) * HDIM + c0);
        float4 hB4 = *(const float4*)(h + (rbase + rB) * HDIM + c0);
        float4 oA, oB;
        oA.x = (fmaxf(cj[0].x + obv[0], 0.f) * swv[0] + sbv[0] + hA4.x) * vfA;
        oA.y = (fmaxf(cj[1].x + obv[1], 0.f) * swv[1] + sbv[1] + hA4.y) * vfA;
        oA.z = (fmaxf(cj[2].x + obv[2], 0.f) * swv[2] + sbv[2] + hA4.z) * vfA;
        oA.w = (fmaxf(cj[3].x + obv[3], 0.f) * swv[3] + sbv[3] + hA4.w) * vfA;
        oB.x = (fmaxf(cj[0].y + obv[0], 0.f) * swv[0] + sbv[0] + hB4.x) * vfB;
        oB.y = (fmaxf(cj[1].y + obv[1], 0.f) * swv[1] + sbv[1] + hB4.y) * vfB;
        oB.z = (fmaxf(cj[2].y + obv[2], 0.f) * swv[2] + sbv[2] + hB4.z) * vfB;
        oB.w = (fmaxf(cj[3].y + obv[3], 0.f) * swv[3] + sbv[3] + hB4.w) * vfB;
        *(float4*)(out + (rbase + rA) * HDIM + c0) = oA;
        *(float4*)(out + (rbase + rB) * HDIM + c0) = oB;
    }
}

#define SMEMB ((128 * 132 + 128 * 128 + 256) * 4)

extern "C" void kernel_launch(void* const* d_in, const int* in_sizes, int n_in,
                              void* d_out, int out_size) {
    const float* h   = (const float*)d_in[0];
    const void*  ei  = d_in[1];
    // d_in[2] = edge_attr (unused by reference)
    const void*  nid = d_in[3];
    const void*  vld = d_in[4];
    // d_in[5] = N_total (constant 16384)
    const float* epsp = (const float*)d_in[6];
    const float* w1  = (const float*)d_in[7];
    const float* b1  = (const float*)d_in[8];
    const float* w2  = (const float*)d_in[9];
    const float* b2  = (const float*)d_in[10];
    const float* ow  = (const float*)d_in[11];
    const float* ob  = (const float*)d_in[12];
    const float* bnw = (const float*)d_in[13];
    const float* bnb = (const float*)d_in[14];
    float* out = (float*)d_out;

    cudaFuncSetAttribute(k_mlp, cudaFuncAttributeMaxDynamicSharedMemorySize, SMEMB);
    cudaFuncSetAttribute(k_out, cudaFuncAttributeMaxDynamicSharedMemorySize, SMEMB);

    k_detect<<<1, 256>>>((const unsigned*)ei, (const unsigned*)nid, (const unsigned*)vld);
    int initN = MROWS * HDIM / 4 + NSEG * HDIM / 4 + NSEG / 4;
    k_init<<<(initN + 255) / 256, 256>>>((const float4*)h, epsp);
    k_edges<<<NEDGE / 8, 256>>>(h, ei);
    k_count<<<MROWS / 256, 256>>>(nid, vld);
    k_mlp<<<MROWS / 128, 256, SMEMB>>>(w1, b1, w2, b2, nid, vld);
    k_div<<<NSEG * HDIM / 4 / 256, 256>>>();
    k_out<<<MROWS / 128, 256, SMEMB>>>(h, ow, ob, bnw, bnb, nid, vld, out);
}

// round 4
// speedup vs baseline: 1.4259x; 1.4259x over previous
#include <cuda_runtime.h>
#include <cuda_bf16.h>
#include <cstdint>

typedef unsigned int u32;
typedef unsigned long long u64;

#define MROWS 262144
#define HDIM  128
#define NEDGE 2097152
#define NSEG  16384
#define APAD  136   // bf16 elems per padded row (272B stride -> conflict-free ldmatrix)
#define WBLK  17408 // 128*136 elems: one hi (or lo) weight block

// ---- device-global scratch (no allocation) ----
__device__ float g_aggr[MROWS * HDIM];
__device__ float g_hc[MROWS * HDIM];
__device__ float g_hsum[NSEG * HDIM];
__device__ float g_cnt[NSEG];
__device__ int   g_ei64, g_nid64, g_vb8;
// pre-transposed [n][k] padded weights, bf16 split: [hi block][lo block]
__device__ __align__(16) __nv_bfloat16 g_w1t[2 * WBLK];
__device__ __align__(16) __nv_bfloat16 g_w2t[2 * WBLK];
__device__ __align__(16) __nv_bfloat16 g_owt[2][2 * WBLK];  // per concat half

// ---- smem layout (bytes) ----
#define SM_SNID 0
#define SM_SVF  512
#define SM_AHI  1024
#define SM_ALO  (1024 + 34816)
#define SM_B    (1024 + 2 * 34816)
#define SMEM_SZ (1024 + 3 * 34816)   // 105472

// ================= helpers =================
__device__ __forceinline__ u32 su32(const void* p) {
    return (u32)__cvta_generic_to_shared(p);
}
__device__ __forceinline__ void ldsm4(u32* r, u32 addr) {
    asm volatile("ldmatrix.sync.aligned.m8n8.x4.shared.b16 {%0,%1,%2,%3}, [%4];"
                 : "=r"(r[0]), "=r"(r[1]), "=r"(r[2]), "=r"(r[3]) : "r"(addr));
}
__device__ __forceinline__ void mma_bf16(float* d, const u32* a, const u32* b) {
    asm volatile(
        "mma.sync.aligned.m16n8k16.row.col.f32.bf16.bf16.f32 "
        "{%0,%1,%2,%3},{%4,%5,%6,%7},{%8,%9},{%0,%1,%2,%3};"
        : "+f"(d[0]), "+f"(d[1]), "+f"(d[2]), "+f"(d[3])
        : "r"(a[0]), "r"(a[1]), "r"(a[2]), "r"(a[3]), "r"(b[0]), "r"(b[1]));
}
__device__ __forceinline__ u32 pack_bf2(float x, float y) {
    return (u32)__bfloat16_as_ushort(__float2bfloat16(x))
         | ((u32)__bfloat16_as_ushort(__float2bfloat16(y)) << 16);
}
// split pair (x,y) into hi/lo bf16, store u32 at element offset `elem`
__device__ __forceinline__ void sstore(char* hi, char* lo, int elem, float x, float y) {
    __nv_bfloat16 hx = __float2bfloat16(x), hy = __float2bfloat16(y);
    *(u32*)(hi + 2 * elem) = (u32)__bfloat16_as_ushort(hx)
                           | ((u32)__bfloat16_as_ushort(hy) << 16);
    *(u32*)(lo + 2 * elem) = pack_bf2(x - __bfloat162float(hx), y - __bfloat162float(hy));
}
// build 64 cols of row r from contiguous fp32 src
__device__ __forceinline__ void buildA_row(const float* src, char* hi, char* lo,
                                           int r, int c0, float scale) {
#pragma unroll
    for (int i = 0; i < 16; ++i) {
        float4 v = ((const float4*)src)[i];
        int e = r * APAD + c0 + 4 * i;
        sstore(hi, lo, e,     v.x * scale, v.y * scale);
        sstore(hi, lo, e + 2, v.z * scale, v.w * scale);
    }
}
__device__ __forceinline__ long long ld_idx(const void* p, int i, int is64) {
    return is64 ? ((const long long*)p)[i] : (long long)((const int*)p)[i];
}
__device__ __forceinline__ float ld_valid(const void* p, int i, int b8) {
    return b8 ? (((const unsigned char*)p)[i] ? 1.0f : 0.0f)
              : (((const int*)p)[i] ? 1.0f : 0.0f);
}

// GEMM pass: acc += A(a)·B^T (+ A(b)·B^T if Ab != null). A,B smem [rows][APAD] bf16.
__device__ __forceinline__ void gemm_pass(const char* Aa, const char* Ab, const char* B,
                                          float acc[2][8][4], int m0, int n0, int lane) {
    const int arow = lane & 15;
    const int acol = (lane & 16) ? 8 : 0;
    const int brow = (lane & 7) + ((lane & 16) ? 8 : 0);
    const int bcol = (lane & 8) ? 8 : 0;
#pragma unroll
    for (int kk = 0; kk < 8; ++kk) {
        const int k0 = kk * 16;
        u32 b[8][2];
#pragma unroll
        for (int bt = 0; bt < 4; ++bt) {
            u32 t[4];
            ldsm4(t, su32(B + ((n0 + bt * 16 + brow) * APAD + k0 + bcol) * 2));
            b[2 * bt][0] = t[0]; b[2 * bt][1] = t[1];
            b[2 * bt + 1][0] = t[2]; b[2 * bt + 1][1] = t[3];
        }
        u32 a[2][4];
#pragma unroll
        for (int mt = 0; mt < 2; ++mt)
            ldsm4(a[mt], su32(Aa + ((m0 + mt * 16 + arow) * APAD + k0 + acol) * 2));
#pragma unroll
        for (int mt = 0; mt < 2; ++mt)
#pragma unroll
            for (int nt = 0; nt < 8; ++nt)
                mma_bf16(acc[mt][nt], a[mt], b[nt]);
        if (Ab) {
#pragma unroll
            for (int mt = 0; mt < 2; ++mt)
                ldsm4(a[mt], su32(Ab + ((m0 + mt * 16 + arow) * APAD + k0 + acol) * 2));
#pragma unroll
            for (int mt = 0; mt < 2; ++mt)
#pragma unroll
                for (int nt = 0; nt < 8; ++nt)
                    mma_bf16(acc[mt][nt], a[mt], b[nt]);
        }
    }
}

__device__ __forceinline__ void loadB(char* sm, const __nv_bfloat16* src, int tid) {
    const float4* s4 = (const float4*)src;
    float4* d4 = (float4*)(sm + SM_B);
    for (int i = tid; i < 2176; i += 256) d4[i] = s4[i];
}

// ================= small kernels =================
__global__ void k_detect(const unsigned* ei, const unsigned* nid, const unsigned* vld) {
    __shared__ int cnt[3];
    int t = threadIdx.x;
    if (t < 3) cnt[t] = 0;
    __syncthreads();
    int nz = 0;
    for (int i = t; i < 1024; i += 256) nz += (ei[2 * i + 1] != 0u);
    if (nz) atomicAdd(&cnt[0], nz);
    nz = 0;
    for (int i = t; i < 1024; i += 256) nz += (nid[2 * i + 1] != 0u);
    if (nz) atomicAdd(&cnt[1], nz);
    nz = 0;
    for (int i = t; i < 256; i += 256) nz += (vld[i] > 1u);
    if (nz) atomicAdd(&cnt[2], nz);
    __syncthreads();
    if (t == 0) {
        g_ei64  = (cnt[0] < 512);
        g_nid64 = (cnt[1] < 512);
        g_vb8   = (cnt[2] > 0);
    }
}

// weight prep: transpose to [n][k] padded APAD, split hi/lo bf16
__global__ void k_prep(const float* __restrict__ w1, const float* __restrict__ w2,
                       const float* __restrict__ ow) {
    int i = blockIdx.x * 256 + threadIdx.x;  // 0..65535
    float v;
    __nv_bfloat16* dst;
    int k, n;
    if (i < 16384)      { k = i >> 7; n = i & 127; v = w1[i]; dst = g_w1t; }
    else if (i < 32768) { int j = i - 16384; k = j >> 7; n = j & 127; v = w2[j]; dst = g_w2t; }
    else {
        int j = i - 32768; k = j >> 7; n = j & 127; v = ow[j];
        dst = g_owt[k >> 7]; k &= 127;
    }
    __nv_bfloat16 hi = __float2bfloat16(v);
    dst[n * APAD + k] = hi;
    dst[WBLK + n * APAD + k] = __float2bfloat16(v - __bfloat162float(hi));
}

__global__ void k_init(const float4* __restrict__ h4, const float* __restrict__ epsp) {
    int i = blockIdx.x * blockDim.x + threadIdx.x;
    const int A4 = MROWS * HDIM / 4, NH4 = NSEG * HDIM / 4, C4 = NSEG / 4;
    if (i < A4) {
        float e1 = 1.0f + *epsp;
        float4 v = h4[i];
        v.x *= e1; v.y *= e1; v.z *= e1; v.w *= e1;
        ((float4*)g_aggr)[i] = v;
    } else if (i < A4 + NH4) {
        ((float4*)g_hsum)[i - A4] = make_float4(0.f, 0.f, 0.f, 0.f);
    } else if (i < A4 + NH4 + C4) {
        ((float4*)g_cnt)[i - A4 - NH4] = make_float4(0.f, 0.f, 0.f, 0.f);
    }
}

__global__ __launch_bounds__(256) void k_edges(const float* __restrict__ h,
                                               const void* __restrict__ ei) {
    int e = blockIdx.x * 8 + (threadIdx.x >> 5);
    int lane = threadIdx.x & 31;
    long long s, d;
    if (g_ei64) {
        const long long* p = (const long long*)ei;
        s = p[e]; d = p[NEDGE + e];
    } else {
        const int* p = (const int*)ei;
        s = p[e]; d = p[NEDGE + e];
    }
    float4 v = *(const float4*)(h + s * HDIM + lane * 4);
    atomicAdd((float4*)(g_aggr + d * HDIM + lane * 4), v);
}

__global__ void k_count(const void* __restrict__ nid, const void* __restrict__ vld) {
    int i = blockIdx.x * blockDim.x + threadIdx.x;
    if (i >= MROWS) return;
    if (ld_valid(vld, i, g_vb8) > 0.f) {
        long long n = ld_idx(nid, i, g_nid64);
        if (n < 0) n = 0;
        atomicAdd(&g_cnt[(int)n], 1.0f);
    }
}

__global__ void k_div() {
    int i4 = blockIdx.x * blockDim.x + threadIdx.x;
    if (i4 >= NSEG * HDIM / 4) return;
    int row = i4 >> 5;
    float inv = 1.0f / fmaxf(g_cnt[row], 1.0f);
    float4 v = ((float4*)g_hsum)[i4];
    v.x *= inv; v.y *= inv; v.z *= inv; v.w *= inv;
    ((float4*)g_hsum)[i4] = v;
}

// ================= fused MLP (HMMA) =================
__global__ __launch_bounds__(256, 2) void k_mlp(const float* __restrict__ b1,
                                                const float* __restrict__ b2,
                                                const void* __restrict__ nid,
                                                const void* __restrict__ vld) {
    extern __shared__ char sm[];
    int* snid = (int*)(sm + SM_SNID);
    float* svf = (float*)(sm + SM_SVF);
    char* Ahi = sm + SM_AHI;
    char* Alo = sm + SM_ALO;
    char* Bs  = sm + SM_B;

    const int tid = threadIdx.x, wid = tid >> 5, lane = tid & 31;
    const int rbase = blockIdx.x * 128;
    const int m0 = (wid & 3) * 32, n0 = (wid >> 2) * 64;

    if (tid < 128) {
        long long n = ld_idx(nid, rbase + tid, g_nid64);
        if (n < 0) n = 0;
        snid[tid] = (int)n;
        svf[tid] = ld_valid(vld, rbase + tid, g_vb8);
    }
    buildA_row(g_aggr + (size_t)(rbase + (tid >> 1)) * HDIM + (tid & 1) * 64,
               Ahi, Alo, tid >> 1, (tid & 1) * 64, 1.0f);
    loadB(sm, g_w1t, tid);
    __syncthreads();

    float acc[2][8][4];
#pragma unroll
    for (int mt = 0; mt < 2; ++mt)
#pragma unroll
        for (int nt = 0; nt < 8; ++nt)
#pragma unroll
            for (int q = 0; q < 4; ++q) acc[mt][nt][q] = 0.f;

    gemm_pass(Ahi, Alo, Bs, acc, m0, n0, lane);
    __syncthreads();
    loadB(sm, g_w1t + WBLK, tid);
    __syncthreads();
    gemm_pass(Ahi, nullptr, Bs, acc, m0, n0, lane);
    __syncthreads();

    // epilogue 1: relu(D + b1) -> split back into A tiles; reset acc
#pragma unroll
    for (int mt = 0; mt < 2; ++mt)
#pragma unroll
        for (int nt = 0; nt < 8; ++nt) {
            int m = m0 + mt * 16 + (lane >> 2);
            int n = n0 + nt * 8 + (lane & 3) * 2;
            float bx = __ldg(b1 + n), by = __ldg(b1 + n + 1);
            float* d = acc[mt][nt];
            sstore(Ahi, Alo, m * APAD + n,
                   fmaxf(d[0] + bx, 0.f), fmaxf(d[1] + by, 0.f));
            sstore(Ahi, Alo, (m + 8) * APAD + n,
                   fmaxf(d[2] + bx, 0.f), fmaxf(d[3] + by, 0.f));
            d[0] = d[1] = d[2] = d[3] = 0.f;
        }
    loadB(sm, g_w2t, tid);
    __syncthreads();
    gemm_pass(Ahi, Alo, Bs, acc, m0, n0, lane);
    __syncthreads();
    loadB(sm, g_w2t + WBLK, tid);
    __syncthreads();
    gemm_pass(Ahi, nullptr, Bs, acc, m0, n0, lane);

    // epilogue 2: hc = (D + b2) * vf -> gmem + hsum atomics
#pragma unroll
    for (int mt = 0; mt < 2; ++mt)
#pragma unroll
        for (int nt = 0; nt < 8; ++nt) {
            int m = m0 + mt * 16 + (lane >> 2);
            int n = n0 + nt * 8 + (lane & 3) * 2;
            float bx = __ldg(b2 + n), by = __ldg(b2 + n + 1);
            float* d = acc[mt][nt];
#pragma unroll
            for (int half = 0; half < 2; ++half) {
                int mm = m + half * 8;
                float vf = svf[mm];
                float2 v = make_float2((d[2 * half] + bx) * vf,
                                       (d[2 * half + 1] + by) * vf);
                *(float2*)(g_hc + (size_t)(rbase + mm) * HDIM + n) = v;
                if (vf > 0.f)
                    atomicAdd((float2*)(g_hsum + (size_t)snid[mm] * HDIM + n), v);
            }
        }
}

// ================= output stage (HMMA) =================
__global__ __launch_bounds__(256, 2) void k_out(const float* __restrict__ h,
                                                const float* __restrict__ ob,
                                                const float* __restrict__ bnw,
                                                const float* __restrict__ bnb,
                                                const void* __restrict__ nid,
                                                const void* __restrict__ vld,
                                                float* __restrict__ out) {
    extern __shared__ char sm[];
    int* snid = (int*)(sm + SM_SNID);
    float* svf = (float*)(sm + SM_SVF);
    char* Ahi = sm + SM_AHI;
    char* Alo = sm + SM_ALO;
    char* Bs  = sm + SM_B;

    const int tid = threadIdx.x, wid = tid >> 5, lane = tid & 31;
    const int rbase = blockIdx.x * 128;
    const int m0 = (wid & 3) * 32, n0 = (wid >> 2) * 64;
    const int r2 = tid >> 1, c02 = (tid & 1) * 64;

    if (tid < 128) {
        long long n = ld_idx(nid, rbase + tid, g_nid64);
        if (n < 0) n = 0;
        snid[tid] = (int)n;
        svf[tid] = ld_valid(vld, rbase + tid, g_vb8);
    }
    buildA_row(g_hc + (size_t)(rbase + r2) * HDIM + c02, Ahi, Alo, r2, c02, 1.0f);
    loadB(sm, g_owt[0], tid);
    __syncthreads();

    float acc[2][8][4];
#pragma unroll
    for (int mt = 0; mt < 2; ++mt)
#pragma unroll
        for (int nt = 0; nt < 8; ++nt)
#pragma unroll
            for (int q = 0; q < 4; ++q) acc[mt][nt][q] = 0.f;

    gemm_pass(Ahi, Alo, Bs, acc, m0, n0, lane);
    __syncthreads();
    loadB(sm, g_owt[0] + WBLK, tid);
    __syncthreads();
    gemm_pass(Ahi, nullptr, Bs, acc, m0, n0, lane);
    __syncthreads();

    // rebuild A <- x_cross = x_agg[nid] * vf ; B <- ow half1
    buildA_row(g_hsum + (size_t)snid[r2] * HDIM + c02, Ahi, Alo, r2, c02, svf[r2]);
    loadB(sm, g_owt[1], tid);
    __syncthreads();
    gemm_pass(Ahi, Alo, Bs, acc, m0, n0, lane);
    __syncthreads();
    loadB(sm, g_owt[1] + WBLK, tid);
    __syncthreads();
    gemm_pass(Ahi, nullptr, Bs, acc, m0, n0, lane);

    // epilogue: out = (relu(D + ob) * bn_s + bn_b + h) * vf
    const float rs = rsqrtf(1.0f + 1e-5f);
#pragma unroll
    for (int mt = 0; mt < 2; ++mt)
#pragma unroll
        for (int nt = 0; nt < 8; ++nt) {
            int m = m0 + mt * 16 + (lane >> 2);
            int n = n0 + nt * 8 + (lane & 3) * 2;
            float obx = __ldg(ob + n), oby = __ldg(ob + n + 1);
            float swx = __ldg(bnw + n) * rs, swy = __ldg(bnw + n + 1) * rs;
            float sbx = __ldg(bnb + n), sby = __ldg(bnb + n + 1);
            float* d = acc[mt][nt];
#pragma unroll
            for (int half = 0; half < 2; ++half) {
                int mm = m + half * 8;
                float vf = svf[mm];
                float2 hv = *(const float2*)(h + (size_t)(rbase + mm) * HDIM + n);
                float2 o;
                o.x = (fmaxf(d[2 * half] + obx, 0.f) * swx + sbx + hv.x) * vf;
                o.y = (fmaxf(d[2 * half + 1] + oby, 0.f) * swy + sby + hv.y) * vf;
                *(float2*)(out + (size_t)(rbase + mm) * HDIM + n) = o;
            }
        }
}

// ================= launch =================
extern "C" void kernel_launch(void* const* d_in, const int* in_sizes, int n_in,
                              void* d_out, int out_size) {
    const float* h   = (const float*)d_in[0];
    const void*  ei  = d_in[1];
    const void*  nid = d_in[3];
    const void*  vld = d_in[4];
    const float* epsp = (const float*)d_in[6];
    const float* w1  = (const float*)d_in[7];
    const float* b1  = (const float*)d_in[8];
    const float* w2  = (const float*)d_in[9];
    const float* b2  = (const float*)d_in[10];
    const float* ow  = (const float*)d_in[11];
    const float* ob  = (const float*)d_in[12];
    const float* bnw = (const float*)d_in[13];
    const float* bnb = (const float*)d_in[14];
    float* out = (float*)d_out;

    cudaFuncSetAttribute(k_mlp, cudaFuncAttributeMaxDynamicSharedMemorySize, SMEM_SZ);
    cudaFuncSetAttribute(k_out, cudaFuncAttributeMaxDynamicSharedMemorySize, SMEM_SZ);

    k_detect<<<1, 256>>>((const unsigned*)ei, (const unsigned*)nid, (const unsigned*)vld);
    k_prep<<<256, 256>>>(w1, w2, ow);
    int initN = MROWS * HDIM / 4 + NSEG * HDIM / 4 + NSEG / 4;
    k_init<<<(initN + 255) / 256, 256>>>((const float4*)h, epsp);
    k_edges<<<NEDGE / 8, 256>>>(h, ei);
    k_count<<<MROWS / 256, 256>>>(nid, vld);
    k_mlp<<<MROWS / 128, 256, SMEM_SZ>>>(b1, b2, nid, vld);
    k_div<<<NSEG * HDIM / 4 / 256, 256>>>();
    k_out<<<MROWS / 128, 256, SMEM_SZ>>>(h, ob, bnw, bnb, nid, vld, out);
}

// round 5
// speedup vs baseline: 1.9861x; 1.3929x over previous
#include <cuda_runtime.h>
#include <cuda_bf16.h>
#include <cstdint>

typedef unsigned int u32;
typedef unsigned long long u64;

#define MROWS 262144
#define HDIM  128
#define NEDGE 2097152
#define NSEG  16384
#define APAD  136   // bf16 elems per padded row (272B stride -> conflict-benign ldmatrix)
#define WBLK  17408 // 128*136 elems: one hi (or lo) weight block

// ---- device-global scratch (no allocation) ----
__device__ float g_aggr[MROWS * HDIM];
__device__ float g_hc[MROWS * HDIM];
__device__ float g_hsum[NSEG * HDIM];
__device__ float g_cnt[NSEG];
__device__ int   g_ei64, g_nid64, g_vb8;
// CSR build
__device__ int g_deg[MROWS];
__device__ int g_rofs[MROWS];
__device__ int g_cur[MROWS];
__device__ int g_bsum[1024];
__device__ int g_srcs[NEDGE];
// pre-transposed [n][k] padded weights, bf16 split: [hi block][lo block]
__device__ __align__(16) __nv_bfloat16 g_w1t[2 * WBLK];
__device__ __align__(16) __nv_bfloat16 g_w2t[2 * WBLK];
__device__ __align__(16) __nv_bfloat16 g_owt[2][2 * WBLK];  // per concat half

// ---- smem layout (bytes) ----
#define SM_SNID 0
#define SM_SVF  512
#define SM_AHI  1024
#define SM_ALO  (1024 + 34816)
#define SM_B    (1024 + 2 * 34816)
#define SMEM_SZ (1024 + 3 * 34816)   // 105472

// ================= helpers =================
__device__ __forceinline__ u32 su32(const void* p) {
    return (u32)__cvta_generic_to_shared(p);
}
__device__ __forceinline__ void ldsm4(u32* r, u32 addr) {
    asm volatile("ldmatrix.sync.aligned.m8n8.x4.shared.b16 {%0,%1,%2,%3}, [%4];"
                 : "=r"(r[0]), "=r"(r[1]), "=r"(r[2]), "=r"(r[3]) : "r"(addr));
}
__device__ __forceinline__ void mma_bf16(float* d, const u32* a, const u32* b) {
    asm volatile(
        "mma.sync.aligned.m16n8k16.row.col.f32.bf16.bf16.f32 "
        "{%0,%1,%2,%3},{%4,%5,%6,%7},{%8,%9},{%0,%1,%2,%3};"
        : "+f"(d[0]), "+f"(d[1]), "+f"(d[2]), "+f"(d[3])
        : "r"(a[0]), "r"(a[1]), "r"(a[2]), "r"(a[3]), "r"(b[0]), "r"(b[1]));
}
__device__ __forceinline__ u32 pack_bf2(float x, float y) {
    return (u32)__bfloat16_as_ushort(__float2bfloat16(x))
         | ((u32)__bfloat16_as_ushort(__float2bfloat16(y)) << 16);
}
// split pair (x,y) into hi/lo bf16, store u32 at element offset `elem`
__device__ __forceinline__ void sstore(char* hi, char* lo, int elem, float x, float y) {
    __nv_bfloat16 hx = __float2bfloat16(x), hy = __float2bfloat16(y);
    *(u32*)(hi + 2 * elem) = (u32)__bfloat16_as_ushort(hx)
                           | ((u32)__bfloat16_as_ushort(hy) << 16);
    *(u32*)(lo + 2 * elem) = pack_bf2(x - __bfloat162float(hx), y - __bfloat162float(hy));
}
__device__ __forceinline__ long long ld_idx(const void* p, int i, int is64) {
    return is64 ? ((const long long*)p)[i] : (long long)((const int*)p)[i];
}
__device__ __forceinline__ float ld_valid(const void* p, int i, int b8) {
    return b8 ? (((const unsigned char*)p)[i] ? 1.0f : 0.0f)
              : (((const int*)p)[i] ? 1.0f : 0.0f);
}

// GEMM pass: acc += A(a)·B^T (+ A(b)·B^T if Ab != null). A,B smem [rows][APAD] bf16.
__device__ __forceinline__ void gemm_pass(const char* Aa, const char* Ab, const char* B,
                                          float acc[2][8][4], int m0, int n0, int lane) {
    const int arow = lane & 15;
    const int acol = (lane & 16) ? 8 : 0;
    const int brow = (lane & 7) + ((lane & 16) ? 8 : 0);
    const int bcol = (lane & 8) ? 8 : 0;
#pragma unroll
    for (int kk = 0; kk < 8; ++kk) {
        const int k0 = kk * 16;
        u32 b[8][2];
#pragma unroll
        for (int bt = 0; bt < 4; ++bt) {
            u32 t[4];
            ldsm4(t, su32(B + ((n0 + bt * 16 + brow) * APAD + k0 + bcol) * 2));
            b[2 * bt][0] = t[0]; b[2 * bt][1] = t[1];
            b[2 * bt + 1][0] = t[2]; b[2 * bt + 1][1] = t[3];
        }
        u32 a[2][4];
#pragma unroll
        for (int mt = 0; mt < 2; ++mt)
            ldsm4(a[mt], su32(Aa + ((m0 + mt * 16 + arow) * APAD + k0 + acol) * 2));
#pragma unroll
        for (int mt = 0; mt < 2; ++mt)
#pragma unroll
            for (int nt = 0; nt < 8; ++nt)
                mma_bf16(acc[mt][nt], a[mt], b[nt]);
        if (Ab) {
#pragma unroll
            for (int mt = 0; mt < 2; ++mt)
                ldsm4(a[mt], su32(Ab + ((m0 + mt * 16 + arow) * APAD + k0 + acol) * 2));
#pragma unroll
            for (int mt = 0; mt < 2; ++mt)
#pragma unroll
                for (int nt = 0; nt < 8; ++nt)
                    mma_bf16(acc[mt][nt], a[mt], b[nt]);
        }
    }
}

__device__ __forceinline__ void loadB(char* sm, const __nv_bfloat16* src, int tid) {
    const float4* s4 = (const float4*)src;
    float4* d4 = (float4*)(sm + SM_B);
    for (int i = tid; i < 2176; i += 256) d4[i] = s4[i];
}

// ================= small kernels =================
__global__ void k_detect(const unsigned* ei, const unsigned* nid, const unsigned* vld) {
    __shared__ int cnt[3];
    int t = threadIdx.x;
    if (t < 3) cnt[t] = 0;
    __syncthreads();
    int nz = 0;
    for (int i = t; i < 1024; i += 256) nz += (ei[2 * i + 1] != 0u);
    if (nz) atomicAdd(&cnt[0], nz);
    nz = 0;
    for (int i = t; i < 1024; i += 256) nz += (nid[2 * i + 1] != 0u);
    if (nz) atomicAdd(&cnt[1], nz);
    nz = 0;
    for (int i = t; i < 256; i += 256) nz += (vld[i] > 1u);
    if (nz) atomicAdd(&cnt[2], nz);
    __syncthreads();
    if (t == 0) {
        g_ei64  = (cnt[0] < 512);
        g_nid64 = (cnt[1] < 512);
        g_vb8   = (cnt[2] > 0);
    }
}

// weight prep: transpose to [n][k] padded APAD, split hi/lo bf16
__global__ void k_prep(const float* __restrict__ w1, const float* __restrict__ w2,
                       const float* __restrict__ ow) {
    int i = blockIdx.x * 256 + threadIdx.x;  // 0..65535
    float v;
    __nv_bfloat16* dst;
    int k, n;
    if (i < 16384)      { k = i >> 7; n = i & 127; v = w1[i]; dst = g_w1t; }
    else if (i < 32768) { int j = i - 16384; k = j >> 7; n = j & 127; v = w2[j]; dst = g_w2t; }
    else {
        int j = i - 32768; k = j >> 7; n = j & 127; v = ow[j];
        dst = g_owt[k >> 7]; k &= 127;
    }
    __nv_bfloat16 hi = __float2bfloat16(v);
    dst[n * APAD + k] = hi;
    dst[WBLK + n * APAD + k] = __float2bfloat16(v - __bfloat162float(hi));
}

// zero hsum, cnt, deg
__global__ void k_zero() {
    int i = blockIdx.x * blockDim.x + threadIdx.x;
    const int NH4 = NSEG * HDIM / 4, C4 = NSEG / 4, D4 = MROWS / 4;
    if (i < NH4) {
        ((float4*)g_hsum)[i] = make_float4(0.f, 0.f, 0.f, 0.f);
    } else if (i < NH4 + C4) {
        ((float4*)g_cnt)[i - NH4] = make_float4(0.f, 0.f, 0.f, 0.f);
    } else if (i < NH4 + C4 + D4) {
        ((int4*)g_deg)[i - NH4 - C4] = make_int4(0, 0, 0, 0);
    }
}

// ---- CSR build: histogram / scan / scatter ----
__global__ __launch_bounds__(256) void k_hist(const void* __restrict__ ei) {
    int e0 = blockIdx.x * 1024 + threadIdx.x;
#pragma unroll
    for (int q = 0; q < 4; ++q) {
        int e = e0 + q * 256;
        int d = (int)ld_idx(ei, NEDGE + e, g_ei64);
        atomicAdd(&g_deg[d], 1);
    }
}

__global__ void k_scanA() {
    __shared__ int s[256];
    int t = threadIdx.x;
    int i = blockIdx.x * 256 + t;
    int v = g_deg[i];
    s[t] = v;
    __syncthreads();
#pragma unroll
    for (int off = 1; off < 256; off <<= 1) {
        int add = (t >= off) ? s[t - off] : 0;
        __syncthreads();
        s[t] += add;
        __syncthreads();
    }
    g_rofs[i] = s[t] - v;
    if (t == 255) g_bsum[blockIdx.x] = s[255];
}

__global__ void k_scanB() {
    __shared__ int s[1024];
    int t = threadIdx.x;
    int v = g_bsum[t];
    s[t] = v;
    __syncthreads();
#pragma unroll
    for (int off = 1; off < 1024; off <<= 1) {
        int add = (t >= off) ? s[t - off] : 0;
        __syncthreads();
        s[t] += add;
        __syncthreads();
    }
    g_bsum[t] = s[t] - v;  // exclusive
}

__global__ void k_scanC() {
    int i = blockIdx.x * 256 + threadIdx.x;
    int ro = g_rofs[i] + g_bsum[i >> 8];
    g_rofs[i] = ro;
    g_cur[i] = ro;
}

__global__ __launch_bounds__(256) void k_scatter(const void* __restrict__ ei) {
    int e0 = blockIdx.x * 1024 + threadIdx.x;
#pragma unroll
    for (int q = 0; q < 4; ++q) {
        int e = e0 + q * 256;
        int s = (int)ld_idx(ei, e, g_ei64);
        int d = (int)ld_idx(ei, NEDGE + e, g_ei64);
        int pos = atomicAdd(&g_cur[d], 1);
        g_srcs[pos] = s;
    }
}

// ---- aggregate: aggr[r] = (1+eps)*h[r] + sum_{s in csr[r]} h[s] (warp per row) ----
__global__ __launch_bounds__(256) void k_aggr(const float* __restrict__ h,
                                              const float* __restrict__ epsp) {
    int r = blockIdx.x * 8 + (threadIdx.x >> 5);
    int lane = threadIdx.x & 31;
    const float4* h4 = (const float4*)h;
    float e1 = 1.0f + *epsp;
    float4 a = h4[(size_t)r * 32 + lane];
    float4 acc0 = make_float4(a.x * e1, a.y * e1, a.z * e1, a.w * e1);
    float4 acc1 = make_float4(0.f, 0.f, 0.f, 0.f);
    int start = g_rofs[r], deg = g_deg[r];
    for (int base = 0; base < deg; base += 32) {
        int n = min(32, deg - base);
        int sidx = (lane < n) ? g_srcs[start + base + lane] : 0;
        for (int e = 0; e < n; e += 2) {
            int s0 = __shfl_sync(0xffffffffu, sidx, e);
            float4 v0 = h4[(size_t)s0 * 32 + lane];
            acc0.x += v0.x; acc0.y += v0.y; acc0.z += v0.z; acc0.w += v0.w;
            if (e + 1 < n) {
                int s1 = __shfl_sync(0xffffffffu, sidx, e + 1);
                float4 v1 = h4[(size_t)s1 * 32 + lane];
                acc1.x += v1.x; acc1.y += v1.y; acc1.z += v1.z; acc1.w += v1.w;
            }
        }
    }
    acc0.x += acc1.x; acc0.y += acc1.y; acc0.z += acc1.z; acc0.w += acc1.w;
    ((float4*)g_aggr)[(size_t)r * 32 + lane] = acc0;
}

__global__ void k_count(const void* __restrict__ nid, const void* __restrict__ vld) {
    int i = blockIdx.x * blockDim.x + threadIdx.x;
    if (i >= MROWS) return;
    if (ld_valid(vld, i, g_vb8) > 0.f) {
        long long n = ld_idx(nid, i, g_nid64);
        if (n < 0) n = 0;
        atomicAdd(&g_cnt[(int)n], 1.0f);
    }
}

__global__ void k_div() {
    int i4 = blockIdx.x * blockDim.x + threadIdx.x;
    if (i4 >= NSEG * HDIM / 4) return;
    int row = i4 >> 5;
    float inv = 1.0f / fmaxf(g_cnt[row], 1.0f);
    float4 v = ((float4*)g_hsum)[i4];
    v.x *= inv; v.y *= inv; v.z *= inv; v.w *= inv;
    ((float4*)g_hsum)[i4] = v;
}

// ================= fused MLP (HMMA) =================
__global__ __launch_bounds__(256, 2) void k_mlp(const float* __restrict__ b1,
                                                const float* __restrict__ b2,
                                                const void* __restrict__ nid,
                                                const void* __restrict__ vld) {
    extern __shared__ char sm[];
    int* snid = (int*)(sm + SM_SNID);
    float* svf = (float*)(sm + SM_SVF);
    char* Ahi = sm + SM_AHI;
    char* Alo = sm + SM_ALO;
    char* Bs  = sm + SM_B;

    const int tid = threadIdx.x, wid = tid >> 5, lane = tid & 31;
    const int rbase = blockIdx.x * 128;
    const int m0 = (wid & 3) * 32, n0 = (wid >> 2) * 64;

    if (tid < 128) {
        long long n = ld_idx(nid, rbase + tid, g_nid64);
        if (n < 0) n = 0;
        snid[tid] = (int)n;
        svf[tid] = ld_valid(vld, rbase + tid, g_vb8);
    }
    // coalesced A build: warp per row, lane = float4 column
    {
        const float* Abase = g_aggr + (size_t)rbase * HDIM;
#pragma unroll
        for (int rr = 0; rr < 16; ++rr) {
            int r = rr * 8 + wid;
            float4 v = *(const float4*)(Abase + (size_t)r * HDIM + lane * 4);
            int e = r * APAD + lane * 4;
            sstore(Ahi, Alo, e, v.x, v.y);
            sstore(Ahi, Alo, e + 2, v.z, v.w);
        }
    }
    loadB(sm, g_w1t, tid);
    __syncthreads();

    float acc[2][8][4];
#pragma unroll
    for (int mt = 0; mt < 2; ++mt)
#pragma unroll
        for (int nt = 0; nt < 8; ++nt)
#pragma unroll
            for (int q = 0; q < 4; ++q) acc[mt][nt][q] = 0.f;

    gemm_pass(Ahi, Alo, Bs, acc, m0, n0, lane);
    __syncthreads();
    loadB(sm, g_w1t + WBLK, tid);
    __syncthreads();
    gemm_pass(Ahi, nullptr, Bs, acc, m0, n0, lane);
    __syncthreads();

    // epilogue 1: relu(D + b1) -> split back into A tiles; reset acc
#pragma unroll
    for (int mt = 0; mt < 2; ++mt)
#pragma unroll
        for (int nt = 0; nt < 8; ++nt) {
            int m = m0 + mt * 16 + (lane >> 2);
            int n = n0 + nt * 8 + (lane & 3) * 2;
            float bx = __ldg(b1 + n), by = __ldg(b1 + n + 1);
            float* d = acc[mt][nt];
            sstore(Ahi, Alo, m * APAD + n,
                   fmaxf(d[0] + bx, 0.f), fmaxf(d[1] + by, 0.f));
            sstore(Ahi, Alo, (m + 8) * APAD + n,
                   fmaxf(d[2] + bx, 0.f), fmaxf(d[3] + by, 0.f));
            d[0] = d[1] = d[2] = d[3] = 0.f;
        }
    loadB(sm, g_w2t, tid);
    __syncthreads();
    gemm_pass(Ahi, Alo, Bs, acc, m0, n0, lane);
    __syncthreads();
    loadB(sm, g_w2t + WBLK, tid);
    __syncthreads();
    gemm_pass(Ahi, nullptr, Bs, acc, m0, n0, lane);

    // epilogue 2: hc = (D + b2) * vf -> gmem + hsum atomics
#pragma unroll
    for (int mt = 0; mt < 2; ++mt)
#pragma unroll
        for (int nt = 0; nt < 8; ++nt) {
            int m = m0 + mt * 16 + (lane >> 2);
            int n = n0 + nt * 8 + (lane & 3) * 2;
            float bx = __ldg(b2 + n), by = __ldg(b2 + n + 1);
            float* d = acc[mt][nt];
#pragma unroll
            for (int half = 0; half < 2; ++half) {
                int mm = m + half * 8;
                float vf = svf[mm];
                float2 v = make_float2((d[2 * half] + bx) * vf,
                                       (d[2 * half + 1] + by) * vf);
                *(float2*)(g_hc + (size_t)(rbase + mm) * HDIM + n) = v;
                if (vf > 0.f)
                    atomicAdd((float2*)(g_hsum + (size_t)snid[mm] * HDIM + n), v);
            }
        }
}

// ================= output stage (HMMA) =================
__global__ __launch_bounds__(256, 2) void k_out(const float* __restrict__ h,
                                                const float* __restrict__ ob,
                                                const float* __restrict__ bnw,
                                                const float* __restrict__ bnb,
                                                const void* __restrict__ nid,
                                                const void* __restrict__ vld,
                                                float* __restrict__ out) {
    extern __shared__ char sm[];
    int* snid = (int*)(sm + SM_SNID);
    float* svf = (float*)(sm + SM_SVF);
    char* Ahi = sm + SM_AHI;
    char* Alo = sm + SM_ALO;
    char* Bs  = sm + SM_B;

    const int tid = threadIdx.x, wid = tid >> 5, lane = tid & 31;
    const int rbase = blockIdx.x * 128;
    const int m0 = (wid & 3) * 32, n0 = (wid >> 2) * 64;

    if (tid < 128) {
        long long n = ld_idx(nid, rbase + tid, g_nid64);
        if (n < 0) n = 0;
        snid[tid] = (int)n;
        svf[tid] = ld_valid(vld, rbase + tid, g_vb8);
    }
    // coalesced A build from hc
    {
        const float* Abase = g_hc + (size_t)rbase * HDIM;
#pragma unroll
        for (int rr = 0; rr < 16; ++rr) {
            int r = rr * 8 + wid;
            float4 v = *(const float4*)(Abase + (size_t)r * HDIM + lane * 4);
            int e = r * APAD + lane * 4;
            sstore(Ahi, Alo, e, v.x, v.y);
            sstore(Ahi, Alo, e + 2, v.z, v.w);
        }
    }
    loadB(sm, g_owt[0], tid);
    __syncthreads();

    float acc[2][8][4];
#pragma unroll
    for (int mt = 0; mt < 2; ++mt)
#pragma unroll
        for (int nt = 0; nt < 8; ++nt)
#pragma unroll
            for (int q = 0; q < 4; ++q) acc[mt][nt][q] = 0.f;

    gemm_pass(Ahi, Alo, Bs, acc, m0, n0, lane);
    __syncthreads();
    loadB(sm, g_owt[0] + WBLK, tid);
    __syncthreads();
    gemm_pass(Ahi, nullptr, Bs, acc, m0, n0, lane);
    __syncthreads();

    // rebuild A <- x_cross = x_agg[nid] * vf (coalesced, warp per row)
#pragma unroll
    for (int rr = 0; rr < 16; ++rr) {
        int r = rr * 8 + wid;
        int seg = snid[r];
        float vf = svf[r];
        float4 v = ((const float4*)(g_hsum + (size_t)seg * HDIM))[lane];
        int e = r * APAD + lane * 4;
        sstore(Ahi, Alo, e, v.x * vf, v.y * vf);
        sstore(Ahi, Alo, e + 2, v.z * vf, v.w * vf);
    }
    loadB(sm, g_owt[1], tid);
    __syncthreads();
    gemm_pass(Ahi, Alo, Bs, acc, m0, n0, lane);
    __syncthreads();
    loadB(sm, g_owt[1] + WBLK, tid);
    __syncthreads();
    gemm_pass(Ahi, nullptr, Bs, acc, m0, n0, lane);

    // epilogue: out = (relu(D + ob) * bn_s + bn_b + h) * vf
    const float rs = rsqrtf(1.0f + 1e-5f);
#pragma unroll
    for (int mt = 0; mt < 2; ++mt)
#pragma unroll
        for (int nt = 0; nt < 8; ++nt) {
            int m = m0 + mt * 16 + (lane >> 2);
            int n = n0 + nt * 8 + (lane & 3) * 2;
            float obx = __ldg(ob + n), oby = __ldg(ob + n + 1);
            float swx = __ldg(bnw + n) * rs, swy = __ldg(bnw + n + 1) * rs;
            float sbx = __ldg(bnb + n), sby = __ldg(bnb + n + 1);
            float* d = acc[mt][nt];
#pragma unroll
            for (int half = 0; half < 2; ++half) {
                int mm = m + half * 8;
                float vf = svf[mm];
                float2 hv = *(const float2*)(h + (size_t)(rbase + mm) * HDIM + n);
                float2 o;
                o.x = (fmaxf(d[2 * half] + obx, 0.f) * swx + sbx + hv.x) * vf;
                o.y = (fmaxf(d[2 * half + 1] + oby, 0.f) * swy + sby + hv.y) * vf;
                *(float2*)(out + (size_t)(rbase + mm) * HDIM + n) = o;
            }
        }
}

// ================= launch =================
extern "C" void kernel_launch(void* const* d_in, const int* in_sizes, int n_in,
                              void* d_out, int out_size) {
    const float* h   = (const float*)d_in[0];
    const void*  ei  = d_in[1];
    const void*  nid = d_in[3];
    const void*  vld = d_in[4];
    const float* epsp = (const float*)d_in[6];
    const float* w1  = (const float*)d_in[7];
    const float* b1  = (const float*)d_in[8];
    const float* w2  = (const float*)d_in[9];
    const float* b2  = (const float*)d_in[10];
    const float* ow  = (const float*)d_in[11];
    const float* ob  = (const float*)d_in[12];
    const float* bnw = (const float*)d_in[13];
    const float* bnb = (const float*)d_in[14];
    float* out = (float*)d_out;

    cudaFuncSetAttribute(k_mlp, cudaFuncAttributeMaxDynamicSharedMemorySize, SMEM_SZ);
    cudaFuncSetAttribute(k_out, cudaFuncAttributeMaxDynamicSharedMemorySize, SMEM_SZ);

    k_detect<<<1, 256>>>((const unsigned*)ei, (const unsigned*)nid, (const unsigned*)vld);
    k_prep<<<256, 256>>>(w1, w2, ow);
    int zeroN = NSEG * HDIM / 4 + NSEG / 4 + MROWS / 4;
    k_zero<<<(zeroN + 255) / 256, 256>>>();
    k_hist<<<NEDGE / 1024, 256>>>(ei);
    k_scanA<<<MROWS / 256, 256>>>();
    k_scanB<<<1, 1024>>>();
    k_scanC<<<MROWS / 256, 256>>>();
    k_scatter<<<NEDGE / 1024, 256>>>(ei);
    k_count<<<MROWS / 256, 256>>>(nid, vld);
    k_aggr<<<MROWS / 8, 256>>>(h, epsp);
    k_mlp<<<MROWS / 128, 256, SMEM_SZ>>>(b1, b2, nid, vld);
    k_div<<<NSEG * HDIM / 4 / 256, 256>>>();
    k_out<<<MROWS / 128, 256, SMEM_SZ>>>(h, ob, bnw, bnb, nid, vld, out);
}